// round 1
// baseline (speedup 1.0000x reference)
#include <cuda_runtime.h>
#include <math.h>

// Problem constants
#define O_NODES 10000
#define T_EDGES 50000
#define DIN     128
#define HH      512
#define DOUTT   128
#define NG      2048    // 4*H (gates)
#define N2      1152    // 2H + DOUT
#define HIST_SZ 131072

// ---------------- scratch (__device__ globals; no allocs allowed) ----------------
__device__ float g_cur [(size_t)T_EDGES * 384];   //  76.8 MB
__device__ float g_mid [(size_t)T_EDGES * HH];    // 102.4 MB
__device__ float g_newt[(size_t)T_EDGES * N2];    // 230.4 MB
__device__ float g_gxs [(size_t)T_EDGES * NG];    // 409.6 MB
__device__ float g_gxo [(size_t)T_EDGES * NG];    // 409.6 MB
__device__ float g_G   [(size_t)O_NODES * NG];    //  81.9 MB
__device__ float g_hs  [(size_t)O_NODES * HH];
__device__ float g_cs  [(size_t)O_NODES * HH];
__device__ float g_prev[(size_t)O_NODES * HH];
__device__ float g_pc  [(size_t)O_NODES * 1024];
__device__ int   g_hist  [HIST_SZ];
__device__ int   g_cursor[HIST_SZ];
__device__ int   g_cnt   [HIST_SZ];
__device__ int   g_order [O_NODES];
__device__ int   g_pos   [O_NODES];

// ---------------- generic SGEMM: C[M,N] = act(A[M,K] @ B[N,K]^T + bias) ----------
// A: row-major with leading dim lda (supports slices of g_newt).
// B: row-major [N, K] (all weight matrices are stored this way).
// mdev: optional device pointer overriding M (LSTM per-step active-row count).
// Requires: N % 128 == 0, K % 8 == 0, pointers 16B-aligned, lda/K % 4 == 0.
template<bool RELU, bool BIAS>
__global__ void __launch_bounds__(256, 2)
sgemm_k(const float* __restrict__ A, int lda,
        const float* __restrict__ B, int K,
        const float* __restrict__ bias,
        float* __restrict__ C, int ldc,
        int M, const int* __restrict__ mdev)
{
    if (mdev) M = *mdev;
    const int m0 = blockIdx.y * 128;
    if (m0 >= M) return;
    const int n0 = blockIdx.x * 128;

    __shared__ float As[8][132];
    __shared__ float Bs[8][132];

    const int tid = threadIdx.x;
    const int lr  = tid >> 1;          // 0..127 : tile row being loaded
    const int lc  = (tid & 1) << 2;    // 0 or 4 : float4 column
    const int tx  = tid & 15;          // 0..15
    const int ty  = tid >> 4;          // 0..15

    float acc[8][8];
#pragma unroll
    for (int i = 0; i < 8; i++)
#pragma unroll
        for (int j = 0; j < 8; j++) acc[i][j] = 0.f;

    for (int k0 = 0; k0 < K; k0 += 8) {
        float4 av = make_float4(0.f, 0.f, 0.f, 0.f);
        if (m0 + lr < M)
            av = *(const float4*)(A + (size_t)(m0 + lr) * lda + (k0 + lc));
        float4 bv = *(const float4*)(B + (size_t)(n0 + lr) * K + (k0 + lc));

        As[lc + 0][lr] = av.x; As[lc + 1][lr] = av.y;
        As[lc + 2][lr] = av.z; As[lc + 3][lr] = av.w;
        Bs[lc + 0][lr] = bv.x; Bs[lc + 1][lr] = bv.y;
        Bs[lc + 2][lr] = bv.z; Bs[lc + 3][lr] = bv.w;
        __syncthreads();

#pragma unroll
        for (int k = 0; k < 8; k++) {
            float4 a0 = *(const float4*)&As[k][ty * 8];
            float4 a1 = *(const float4*)&As[k][ty * 8 + 4];
            float4 b0 = *(const float4*)&Bs[k][tx * 8];
            float4 b1 = *(const float4*)&Bs[k][tx * 8 + 4];
            float ra[8] = {a0.x, a0.y, a0.z, a0.w, a1.x, a1.y, a1.z, a1.w};
            float rb[8] = {b0.x, b0.y, b0.z, b0.w, b1.x, b1.y, b1.z, b1.w};
#pragma unroll
            for (int i = 0; i < 8; i++)
#pragma unroll
                for (int j = 0; j < 8; j++)
                    acc[i][j] = fmaf(ra[i], rb[j], acc[i][j]);
        }
        __syncthreads();
    }

    float bb[8];
    if (BIAS) {
#pragma unroll
        for (int j = 0; j < 8; j++) bb[j] = bias[n0 + tx * 8 + j];
    }
#pragma unroll
    for (int i = 0; i < 8; i++) {
        int row = m0 + ty * 8 + i;
        if (row >= M) break;                      // thread's rows are contiguous
        float* crow = C + (size_t)row * ldc + n0 + tx * 8;
#pragma unroll
        for (int j = 0; j < 8; j++) {
            float v = acc[i][j];
            if (BIAS) v += bb[j];
            if (RELU) v = fmaxf(v, 0.f);
            crow[j] = v;
        }
    }
}

// ---------------- helpers -----------------------------------------------------
__global__ void k_zero_hist()
{
    int i = blockIdx.x * blockDim.x + threadIdx.x;
    if (i < HIST_SZ) g_hist[i] = 0;
}

__global__ void k_init_hc()
{
    int i = blockIdx.x * blockDim.x + threadIdx.x;
    if (i < O_NODES * HH / 4) {
        ((float4*)g_hs)[i] = make_float4(0.f, 0.f, 0.f, 0.f);
        ((float4*)g_cs)[i] = make_float4(0.f, 0.f, 0.f, 0.f);
    }
}

__global__ void k_hist(const int* __restrict__ lengths)
{
    int n = blockIdx.x * blockDim.x + threadIdx.x;
    if (n < O_NODES) atomicAdd(&g_hist[lengths[n]], 1);
}

// Descending counting-sort scan.  After this:
//   g_cursor[len] = index at which nodes of length `len` begin (desc order)
//   g_cnt[t]      = number of nodes with length > t (= active rows at step t)
__global__ void k_scan(int L)
{
    int run = 0;
    for (int len = L; len >= 0; --len) {
        g_cursor[len] = run;
        g_cnt[len]    = run;
        run += g_hist[len];
    }
}

__global__ void k_scatter(const int* __restrict__ lengths)
{
    int n = blockIdx.x * blockDim.x + threadIdx.x;
    if (n >= O_NODES) return;
    int pos = atomicAdd(&g_cursor[lengths[n]], 1);
    g_order[pos] = n;
    g_pos[n] = pos;
}

// cur_t = [obj[s] | pred | obj[o]]  as float4 gather (96 float4 per edge)
__global__ void k_build_cur(const float* __restrict__ obj,
                            const float* __restrict__ pred,
                            const int*   __restrict__ edges)
{
    int i = blockIdx.x * blockDim.x + threadIdx.x;
    if (i >= T_EDGES * 96) return;
    int e = i / 96, q = i - e * 96;
    float4 v;
    if (q < 32) {
        int s = edges[2 * e];
        v = ((const float4*)obj)[(size_t)s * 32 + q];
    } else if (q < 64) {
        v = ((const float4*)pred)[(size_t)e * 32 + (q - 32)];
    } else {
        int o = edges[2 * e + 1];
        v = ((const float4*)obj)[(size_t)o * 32 + (q - 64)];
    }
    ((float4*)g_cur)[(size_t)e * 96 + q] = v;
}

// new_p = new_t[:, 512:640] -> out[O*DOUT : ]
__global__ void k_copy_newp(float* __restrict__ out)
{
    int i = blockIdx.x * blockDim.x + threadIdx.x;
    if (i >= T_EDGES * 32) return;
    int e = i / 32, q = i - e * 32;
    ((float4*)out)[(size_t)(O_NODES * DOUTT / 4) + (size_t)e * 32 + q] =
        ((const float4*)g_newt)[(size_t)e * 288 + 128 + q];
}

__device__ __forceinline__ float sigm(float x) { return 1.f / (1.f + expf(-x)); }

// One LSTM step for active (sorted) rows: g = G(row) + GX(nbr) + bih + bhh
__global__ void k_lstm_update(int t, int L,
                              const int*   __restrict__ nbr,
                              const float* __restrict__ bih,
                              const float* __restrict__ bhh)
{
    int row = blockIdx.x;
    if (row >= g_cnt[t]) return;
    int j = threadIdx.x;                     // 0..511
    int node = g_order[row];
    int idx  = nbr[(size_t)node * L + t];

    const float* Gr = g_G + (size_t)row * NG;
    float gi = Gr[j];
    float gf = Gr[512 + j];
    float gg = Gr[1024 + j];
    float go = Gr[1536 + j];

    if (idx > 0) {
        const float* gx = (idx <= T_EDGES)
            ? g_gxs + (size_t)(idx - 1) * NG
            : g_gxo + (size_t)(idx - 1 - T_EDGES) * NG;
        gi += gx[j]; gf += gx[512 + j]; gg += gx[1024 + j]; go += gx[1536 + j];
    }
    gi += bih[j]        + bhh[j];
    gf += bih[512 + j]  + bhh[512 + j];
    gg += bih[1024 + j] + bhh[1024 + j];
    go += bih[1536 + j] + bhh[1536 + j];

    float c  = g_cs[(size_t)row * HH + j];
    float c2 = sigm(gf) * c + sigm(gi) * tanhf(gg);
    float h2 = sigm(go) * tanhf(c2);
    g_cs[(size_t)row * HH + j] = c2;
    g_hs[(size_t)row * HH + j] = h2;
}

// pooled_cat[n] = [ h(sorted pos of n) | prev[n] ]
__global__ void k_build_pc()
{
    int i = blockIdx.x * blockDim.x + threadIdx.x;
    if (i >= O_NODES * 256) return;
    int n = i >> 8, q = i & 255;
    float4 v;
    if (q < 128) v = ((const float4*)g_hs)[(size_t)g_pos[n] * 128 + q];
    else         v = ((const float4*)g_prev)[(size_t)n * 128 + (q - 128)];
    ((float4*)g_pc)[(size_t)n * 256 + q] = v;
}

// ---------------- launcher -----------------------------------------------------
extern "C" void kernel_launch(void* const* d_in, const int* in_sizes, int n_in,
                              void* d_out, int out_size)
{
    const float* obj    = (const float*)d_in[0];
    const float* pred   = (const float*)d_in[1];
    const int*   edges  = (const int*)  d_in[2];
    const int*   nbr    = (const int*)  d_in[3];
    const int*   lengths= (const int*)  d_in[4];
    const float* W1     = (const float*)d_in[5];
    const float* b1     = (const float*)d_in[6];
    const float* W2     = (const float*)d_in[7];
    const float* b2     = (const float*)d_in[8];
    const float* Wih    = (const float*)d_in[9];
    const float* Whh    = (const float*)d_in[10];
    const float* bih    = (const float*)d_in[11];
    const float* bhh    = (const float*)d_in[12];
    const float* Wproj  = (const float*)d_in[13];
    const float* bproj  = (const float*)d_in[14];
    const float* Wout   = (const float*)d_in[15];
    const float* bout   = (const float*)d_in[16];
    float* out = (float*)d_out;

    const int L = in_sizes[3] / O_NODES;

    float *p_cur, *p_mid, *p_newt, *p_gxs, *p_gxo, *p_G, *p_hs, *p_prev, *p_pc;
    int *p_cnt;
    cudaGetSymbolAddress((void**)&p_cur,  g_cur);
    cudaGetSymbolAddress((void**)&p_mid,  g_mid);
    cudaGetSymbolAddress((void**)&p_newt, g_newt);
    cudaGetSymbolAddress((void**)&p_gxs,  g_gxs);
    cudaGetSymbolAddress((void**)&p_gxo,  g_gxo);
    cudaGetSymbolAddress((void**)&p_G,    g_G);
    cudaGetSymbolAddress((void**)&p_hs,   g_hs);
    cudaGetSymbolAddress((void**)&p_prev, g_prev);
    cudaGetSymbolAddress((void**)&p_pc,   g_pc);
    cudaGetSymbolAddress((void**)&p_cnt,  g_cnt);

    const int MT_E = (T_EDGES + 127) / 128;   // 391
    const int MT_O = (O_NODES + 127) / 128;   // 79

    // node sort by length (descending) + state init
    k_zero_hist<<<HIST_SZ / 256, 256>>>();
    k_init_hc<<<(O_NODES * HH / 4 + 255) / 256, 256>>>();
    k_hist<<<(O_NODES + 255) / 256, 256>>>(lengths);
    k_scan<<<1, 1>>>(L);
    k_scatter<<<(O_NODES + 255) / 256, 256>>>(lengths);

    // edge MLP
    k_build_cur<<<(T_EDGES * 96 + 255) / 256, 256>>>(obj, pred, edges);
    sgemm_k<true,  true ><<<dim3(4,  MT_E), 256>>>(p_cur, 384, W1, 384, b1, p_mid, 512,  T_EDGES, nullptr);
    sgemm_k<true,  true ><<<dim3(9,  MT_E), 256>>>(p_mid, 512, W2, 512, b2, p_newt, N2, T_EDGES, nullptr);
    k_copy_newp<<<(T_EDGES * 32 + 255) / 256, 256>>>(out);

    // LSTM input-gate precompute: GXs = new_s @ Wih^T, GXo = new_o @ Wih^T
    sgemm_k<false, false><<<dim3(16, MT_E), 256>>>(p_newt,       N2, Wih, 512, nullptr, p_gxs, NG, T_EDGES, nullptr);
    sgemm_k<false, false><<<dim3(16, MT_E), 256>>>(p_newt + 640, N2, Wih, 512, nullptr, p_gxo, NG, T_EDGES, nullptr);

    // prev = obj @ Wproj^T + bproj (independent, can go anywhere)
    sgemm_k<false, true ><<<dim3(4,  MT_O), 256>>>(obj, 128, Wproj, 128, bproj, p_prev, 512, O_NODES, nullptr);

    // LSTM recurrence: per step, dense GEMM over active prefix + pointwise update
    for (int t = 0; t < L; ++t) {
        sgemm_k<false, false><<<dim3(16, MT_O), 256>>>(p_hs, 512, Whh, 512, nullptr, p_G, NG, O_NODES, p_cnt + t);
        k_lstm_update<<<O_NODES, 512>>>(t, L, nbr, bih, bhh);
    }

    // new_obj = [pooled | prev] @ Wout^T + bout
    k_build_pc<<<(O_NODES * 256 + 255) / 256, 256>>>();
    sgemm_k<false, true ><<<dim3(1,  MT_O), 256>>>(p_pc, 1024, Wout, 1024, bout, out, 128, O_NODES, nullptr);
}

// round 3
// speedup vs baseline: 2.8424x; 2.8424x over previous
#include <cuda_runtime.h>
#include <cstdint>
#include <math.h>

// Problem constants
#define O_NODES 10000
#define T_EDGES 50000
#define DIN     128
#define HH      512
#define DOUTT   128
#define NG      2048    // 4*H (gates)
#define N2      1152    // 2H + DOUT
#define HIST_SZ 131072

// ---------------- scratch (__device__ globals; no allocs allowed) ----------------
__device__ float g_cur [(size_t)T_EDGES * 384];
__device__ float g_mid [(size_t)T_EDGES * HH];
__device__ float g_newt[(size_t)T_EDGES * N2];
__device__ float g_gxs [(size_t)T_EDGES * NG];
__device__ float g_gxo [(size_t)T_EDGES * NG];
__device__ float g_G   [(size_t)O_NODES * NG];
__device__ float g_hs  [(size_t)O_NODES * HH];
__device__ float g_cs  [(size_t)O_NODES * HH];
__device__ float g_prev[(size_t)O_NODES * HH];
__device__ float g_pc  [(size_t)O_NODES * 1024];
__device__ int   g_hist  [HIST_SZ];
__device__ int   g_cursor[HIST_SZ];
__device__ int   g_cnt   [HIST_SZ];
__device__ int   g_order [O_NODES];
__device__ int   g_pos   [O_NODES];

// ---------------- tf32 tensor-core GEMM --------------------------------------
// C[M,N] = act(A[M,K] @ B[N,K]^T + bias)
// Block tile 128x128, BK=16, double-buffered cp.async, 8 warps x (64x32).
// Requires N % 128 == 0, K % 16 == 0, 16B-aligned pointers, lda*4 % 16 == 0.

__device__ __forceinline__ unsigned f2tf(float x) {
    unsigned u;
    asm("cvt.rna.tf32.f32 %0, %1;" : "=r"(u) : "f"(x));
    return u;
}

__device__ __forceinline__ void mma_tf32(float* d, const unsigned* a, const unsigned* b) {
    asm volatile(
        "mma.sync.aligned.m16n8k8.row.col.f32.tf32.tf32.f32 "
        "{%0,%1,%2,%3}, {%4,%5,%6,%7}, {%8,%9}, {%0,%1,%2,%3};\n"
        : "+f"(d[0]), "+f"(d[1]), "+f"(d[2]), "+f"(d[3])
        : "r"(a[0]), "r"(a[1]), "r"(a[2]), "r"(a[3]), "r"(b[0]), "r"(b[1]));
}

__device__ __forceinline__ void cpa16(unsigned sdst, const float* gsrc, int src_bytes) {
    asm volatile("cp.async.cg.shared.global [%0], [%1], 16, %2;\n"
                 :: "r"(sdst), "l"(gsrc), "r"(src_bytes) : "memory");
}
__device__ __forceinline__ void cpa_commit() {
    asm volatile("cp.async.commit_group;\n" ::: "memory");
}
template<int N>
__device__ __forceinline__ void cpa_wait() {
    asm volatile("cp.async.wait_group %0;\n" :: "n"(N) : "memory");
}

template<bool RELU, bool BIAS>
__global__ void __launch_bounds__(256, 2)
tgemm_k(const float* __restrict__ A, int lda,
        const float* __restrict__ B, int K,
        const float* __restrict__ bias,
        float* __restrict__ C, int ldc,
        int M, const int* __restrict__ mdev)
{
    if (mdev) M = *mdev;
    const int m0 = blockIdx.y * 128;
    if (m0 >= M) return;
    const int n0 = blockIdx.x * 128;

    __shared__ float As[2][128][20];   // stride 20 -> conflict-free frag loads
    __shared__ float Bs[2][128][20];

    const int tid  = threadIdx.x;
    const int warp = tid >> 5, lane = tid & 31;
    const int r = lane >> 2, c = lane & 3;
    const int wm = (warp & 1) * 64;    // warp M offset
    const int wn = (warp >> 1) * 32;   // warp N offset

    // loader mapping: 2 threads per row, 2 float4 each
    const int lrow = tid >> 1;
    const int lf4  = (tid & 1) * 2;

    const float* Aptr = A + (size_t)(m0 + lrow) * lda + lf4 * 4;
    const float* Bptr = B + (size_t)(n0 + lrow) * K   + lf4 * 4;
    const int abytes = ((m0 + lrow) < M) ? 16 : 0;

    unsigned sa0 = (unsigned)__cvta_generic_to_shared(&As[0][lrow][lf4 * 4]);
    unsigned sb0 = (unsigned)__cvta_generic_to_shared(&Bs[0][lrow][lf4 * 4]);
    const unsigned bufstride = 128 * 20 * 4;

    float acc[4][4][4];
#pragma unroll
    for (int i = 0; i < 4; i++)
#pragma unroll
        for (int j = 0; j < 4; j++)
#pragma unroll
            for (int q = 0; q < 4; q++) acc[i][j][q] = 0.f;

    const int nk = K >> 4;

    // prologue: tile 0 into buffer 0
#pragma unroll
    for (int i = 0; i < 2; i++) {
        cpa16(sa0 + i * 16, Aptr + i * 4, abytes);
        cpa16(sb0 + i * 16, Bptr + i * 4, 16);
    }
    cpa_commit();

    for (int it = 0; it < nk; ++it) {
        if (it + 1 < nk) {
            int nb = (it + 1) & 1;
            int ko = (it + 1) << 4;
#pragma unroll
            for (int i = 0; i < 2; i++) {
                cpa16(sa0 + nb * bufstride + i * 16, Aptr + ko + i * 4, abytes);
                cpa16(sb0 + nb * bufstride + i * 16, Bptr + ko + i * 4, 16);
            }
            cpa_commit();
            cpa_wait<1>();
        } else {
            cpa_wait<0>();
        }
        __syncthreads();

        const int buf = it & 1;
#pragma unroll
        for (int kk = 0; kk < 16; kk += 8) {
            unsigned ua[4][4], ub[4][2];
#pragma unroll
            for (int mt = 0; mt < 4; mt++) {
                int mb = wm + mt * 16 + r;
                ua[mt][0] = f2tf(As[buf][mb    ][kk + c    ]);
                ua[mt][1] = f2tf(As[buf][mb + 8][kk + c    ]);
                ua[mt][2] = f2tf(As[buf][mb    ][kk + c + 4]);
                ua[mt][3] = f2tf(As[buf][mb + 8][kk + c + 4]);
            }
#pragma unroll
            for (int nt = 0; nt < 4; nt++) {
                int nb = wn + nt * 8 + r;
                ub[nt][0] = f2tf(Bs[buf][nb][kk + c    ]);
                ub[nt][1] = f2tf(Bs[buf][nb][kk + c + 4]);
            }
#pragma unroll
            for (int mt = 0; mt < 4; mt++)
#pragma unroll
                for (int nt = 0; nt < 4; nt++)
                    mma_tf32(acc[mt][nt], ua[mt], ub[nt]);
        }
        __syncthreads();
    }

    // epilogue
#pragma unroll
    for (int mt = 0; mt < 4; mt++) {
        int row0 = m0 + wm + mt * 16 + r;
#pragma unroll
        for (int nt = 0; nt < 4; nt++) {
            int col = n0 + wn + nt * 8 + c * 2;
            float bx = 0.f, by = 0.f;
            if (BIAS) { bx = bias[col]; by = bias[col + 1]; }
            if (row0 < M) {
                float vx = acc[mt][nt][0] + bx;
                float vy = acc[mt][nt][1] + by;
                if (RELU) { vx = fmaxf(vx, 0.f); vy = fmaxf(vy, 0.f); }
                *(float2*)(C + (size_t)row0 * ldc + col) = make_float2(vx, vy);
            }
            if (row0 + 8 < M) {
                float vx = acc[mt][nt][2] + bx;
                float vy = acc[mt][nt][3] + by;
                if (RELU) { vx = fmaxf(vx, 0.f); vy = fmaxf(vy, 0.f); }
                *(float2*)(C + (size_t)(row0 + 8) * ldc + col) = make_float2(vx, vy);
            }
        }
    }
}

// ---------------- helpers -----------------------------------------------------
__global__ void k_zero_hist()
{
    int i = blockIdx.x * blockDim.x + threadIdx.x;
    if (i < HIST_SZ) g_hist[i] = 0;
}

__global__ void k_init_hc()
{
    int i = blockIdx.x * blockDim.x + threadIdx.x;
    if (i < O_NODES * HH / 4) {
        ((float4*)g_hs)[i] = make_float4(0.f, 0.f, 0.f, 0.f);
        ((float4*)g_cs)[i] = make_float4(0.f, 0.f, 0.f, 0.f);
    }
}

__global__ void k_hist(const int* __restrict__ lengths)
{
    int n = blockIdx.x * blockDim.x + threadIdx.x;
    if (n < O_NODES) atomicAdd(&g_hist[lengths[n]], 1);
}

__global__ void k_scan(int L)
{
    int run = 0;
    for (int len = L; len >= 0; --len) {
        g_cursor[len] = run;
        g_cnt[len]    = run;
        run += g_hist[len];
    }
}

__global__ void k_scatter(const int* __restrict__ lengths)
{
    int n = blockIdx.x * blockDim.x + threadIdx.x;
    if (n >= O_NODES) return;
    int pos = atomicAdd(&g_cursor[lengths[n]], 1);
    g_order[pos] = n;
    g_pos[n] = pos;
}

__global__ void k_build_cur(const float* __restrict__ obj,
                            const float* __restrict__ pred,
                            const int*   __restrict__ edges)
{
    int i = blockIdx.x * blockDim.x + threadIdx.x;
    if (i >= T_EDGES * 96) return;
    int e = i / 96, q = i - e * 96;
    float4 v;
    if (q < 32) {
        int s = edges[2 * e];
        v = ((const float4*)obj)[(size_t)s * 32 + q];
    } else if (q < 64) {
        v = ((const float4*)pred)[(size_t)e * 32 + (q - 32)];
    } else {
        int o = edges[2 * e + 1];
        v = ((const float4*)obj)[(size_t)o * 32 + (q - 64)];
    }
    ((float4*)g_cur)[(size_t)e * 96 + q] = v;
}

__global__ void k_copy_newp(float* __restrict__ out)
{
    int i = blockIdx.x * blockDim.x + threadIdx.x;
    if (i >= T_EDGES * 32) return;
    int e = i / 32, q = i - e * 32;
    ((float4*)out)[(size_t)(O_NODES * DOUTT / 4) + (size_t)e * 32 + q] =
        ((const float4*)g_newt)[(size_t)e * 288 + 128 + q];
}

__device__ __forceinline__ float sigm(float x) { return 1.f / (1.f + expf(-x)); }

__global__ void k_lstm_update(int t, int L,
                              const int*   __restrict__ nbr,
                              const float* __restrict__ bih,
                              const float* __restrict__ bhh)
{
    int row = blockIdx.x;
    if (row >= g_cnt[t]) return;
    int j = threadIdx.x;
    int node = g_order[row];
    int idx  = nbr[(size_t)node * L + t];

    const float* Gr = g_G + (size_t)row * NG;
    float gi = Gr[j];
    float gf = Gr[512 + j];
    float gg = Gr[1024 + j];
    float go = Gr[1536 + j];

    if (idx > 0) {
        const float* gx = (idx <= T_EDGES)
            ? g_gxs + (size_t)(idx - 1) * NG
            : g_gxo + (size_t)(idx - 1 - T_EDGES) * NG;
        gi += gx[j]; gf += gx[512 + j]; gg += gx[1024 + j]; go += gx[1536 + j];
    }
    gi += bih[j]        + bhh[j];
    gf += bih[512 + j]  + bhh[512 + j];
    gg += bih[1024 + j] + bhh[1024 + j];
    go += bih[1536 + j] + bhh[1536 + j];

    float cc = g_cs[(size_t)row * HH + j];
    float c2 = sigm(gf) * cc + sigm(gi) * tanhf(gg);
    float h2 = sigm(go) * tanhf(c2);
    g_cs[(size_t)row * HH + j] = c2;
    g_hs[(size_t)row * HH + j] = h2;
}

__global__ void k_build_pc()
{
    int i = blockIdx.x * blockDim.x + threadIdx.x;
    if (i >= O_NODES * 256) return;
    int n = i >> 8, q = i & 255;
    float4 v;
    if (q < 128) v = ((const float4*)g_hs)[(size_t)g_pos[n] * 128 + q];
    else         v = ((const float4*)g_prev)[(size_t)n * 128 + (q - 128)];
    ((float4*)g_pc)[(size_t)n * 256 + q] = v;
}

// ---------------- launcher -----------------------------------------------------
extern "C" void kernel_launch(void* const* d_in, const int* in_sizes, int n_in,
                              void* d_out, int out_size)
{
    const float* obj    = (const float*)d_in[0];
    const float* pred   = (const float*)d_in[1];
    const int*   edges  = (const int*)  d_in[2];
    const int*   nbr    = (const int*)  d_in[3];
    const int*   lengths= (const int*)  d_in[4];
    const float* W1     = (const float*)d_in[5];
    const float* b1     = (const float*)d_in[6];
    const float* W2     = (const float*)d_in[7];
    const float* b2     = (const float*)d_in[8];
    const float* Wih    = (const float*)d_in[9];
    const float* Whh    = (const float*)d_in[10];
    const float* bih    = (const float*)d_in[11];
    const float* bhh    = (const float*)d_in[12];
    const float* Wproj  = (const float*)d_in[13];
    const float* bproj  = (const float*)d_in[14];
    const float* Wout   = (const float*)d_in[15];
    const float* bout   = (const float*)d_in[16];
    float* out = (float*)d_out;

    const int L = in_sizes[3] / O_NODES;

    float *p_cur, *p_mid, *p_newt, *p_gxs, *p_gxo, *p_G, *p_hs, *p_prev, *p_pc;
    int *p_cnt;
    cudaGetSymbolAddress((void**)&p_cur,  g_cur);
    cudaGetSymbolAddress((void**)&p_mid,  g_mid);
    cudaGetSymbolAddress((void**)&p_newt, g_newt);
    cudaGetSymbolAddress((void**)&p_gxs,  g_gxs);
    cudaGetSymbolAddress((void**)&p_gxo,  g_gxo);
    cudaGetSymbolAddress((void**)&p_G,    g_G);
    cudaGetSymbolAddress((void**)&p_hs,   g_hs);
    cudaGetSymbolAddress((void**)&p_prev, g_prev);
    cudaGetSymbolAddress((void**)&p_pc,   g_pc);
    cudaGetSymbolAddress((void**)&p_cnt,  g_cnt);

    const int MT_E = (T_EDGES + 127) / 128;   // 391
    const int MT_O = (O_NODES + 127) / 128;   // 79

    // node sort by length (descending) + state init
    k_zero_hist<<<HIST_SZ / 256, 256>>>();
    k_init_hc<<<(O_NODES * HH / 4 + 255) / 256, 256>>>();
    k_hist<<<(O_NODES + 255) / 256, 256>>>(lengths);
    k_scan<<<1, 1>>>(L);
    k_scatter<<<(O_NODES + 255) / 256, 256>>>(lengths);

    // edge MLP
    k_build_cur<<<(T_EDGES * 96 + 255) / 256, 256>>>(obj, pred, edges);
    tgemm_k<true,  true ><<<dim3(4,  MT_E), 256>>>(p_cur, 384, W1, 384, b1, p_mid, 512,  T_EDGES, nullptr);
    tgemm_k<true,  true ><<<dim3(9,  MT_E), 256>>>(p_mid, 512, W2, 512, b2, p_newt, N2, T_EDGES, nullptr);
    k_copy_newp<<<(T_EDGES * 32 + 255) / 256, 256>>>(out);

    // LSTM input-gate precompute: GXs = new_s @ Wih^T, GXo = new_o @ Wih^T
    tgemm_k<false, false><<<dim3(16, MT_E), 256>>>(p_newt,       N2, Wih, 512, nullptr, p_gxs, NG, T_EDGES, nullptr);
    tgemm_k<false, false><<<dim3(16, MT_E), 256>>>(p_newt + 640, N2, Wih, 512, nullptr, p_gxo, NG, T_EDGES, nullptr);

    // prev = obj @ Wproj^T + bproj
    tgemm_k<false, true ><<<dim3(4,  MT_O), 256>>>(obj, 128, Wproj, 128, bproj, p_prev, 512, O_NODES, nullptr);

    // LSTM recurrence
    for (int t = 0; t < L; ++t) {
        tgemm_k<false, false><<<dim3(16, MT_O), 256>>>(p_hs, 512, Whh, 512, nullptr, p_G, NG, O_NODES, p_cnt + t);
        k_lstm_update<<<O_NODES, 512>>>(t, L, nbr, bih, bhh);
    }

    // new_obj = [pooled | prev] @ Wout^T + bout
    k_build_pc<<<(O_NODES * 256 + 255) / 256, 256>>>();
    tgemm_k<false, true ><<<dim3(1,  MT_O), 256>>>(p_pc, 1024, Wout, 1024, bout, out, 128, O_NODES, nullptr);
}